// round 12
// baseline (speedup 1.0000x reference)
#include <cuda_runtime.h>

#define B_     8
#define N_     16384
#define DIM_   128

// ---------------- scratch (device globals) ----------------------------------
__device__ float g_xr[16777216];   // tf32-rounded, k-permuted x (B,N,128)
__device__ float g_fxt[67108864];  // conv_fx TRANSPOSED (B,512co,16384n)
__device__ float g_xm[67108864];   // conv_x output (B,N,512)
__device__ float g_swt[67108864];  // slice weights TRANSPOSED (B,H,64g,16384n)
__device__ float g_part[4194304];  // 16 chunks x 64 bh x 4096
__device__ float g_npart[262144];  // 64 bh x 64 tiles x 64 g
__device__ float g_st[262144];
__device__ float g_norm[4096];
__device__ float g_q[262144];
__device__ float g_k[262144];
__device__ float g_v[262144];
__device__ float g_os[262144];
__device__ float g_ow[524288];     // OW (B, 512k, 128d)
__device__ float g_wt[1179648];    // tf32, k-permuted weights [1024 co][1152 k]

__device__ __forceinline__ unsigned cvt_tf32(float f) {
    unsigned u;
    asm("cvt.rna.tf32.f32 %0, %1;" : "=r"(u) : "f"(f));
    return u;
}
__device__ __forceinline__ void split_tf32(float v, unsigned& hi, unsigned& lo) {
    hi = cvt_tf32(v);
    lo = cvt_tf32(v - __uint_as_float(hi));
}
__device__ __forceinline__ unsigned smem_u32(const void* p) {
    unsigned a;
    asm("{ .reg .u64 t; cvta.to.shared.u64 t, %1; cvt.u32.u64 %0, t; }"
        : "=r"(a) : "l"(p));
    return a;
}
__device__ __forceinline__ void mma_tf32(float* c, const unsigned* a, const unsigned* b) {
    asm volatile("mma.sync.aligned.m16n8k8.row.col.f32.tf32.tf32.f32 "
                 "{%0,%1,%2,%3}, {%4,%5,%6,%7}, {%8,%9}, {%0,%1,%2,%3};"
                 : "+f"(c[0]), "+f"(c[1]), "+f"(c[2]), "+f"(c[3])
                 : "r"(a[0]), "r"(a[1]), "r"(a[2]), "r"(a[3]),
                   "r"(b[0]), "r"(b[1]));
}
#define CP16(dst, src) \
    asm volatile("cp.async.cg.shared.global [%0], [%1], 16;" :: "r"(dst), "l"(src))
#define CP16Z(dst, src, sz) \
    asm volatile("cp.async.cg.shared.global [%0], [%1], 16, %2;" :: "r"(dst), "l"(src), "r"(sz))
#define CP_COMMIT() asm volatile("cp.async.commit_group;")
#define CP_WAIT(n)  asm volatile("cp.async.wait_group %0;" :: "n"(n))

// ---------------- prep: weights/x tf32 + k-interleave ------------------------
// within each 32-k group: pos = (k%4)*8 + k/4  (mma fragments become float4)
__global__ void wprep_kernel(const float* __restrict__ wfx,
                             const float* __restrict__ wx)
{
    int idx = blockIdx.x * 256 + threadIdx.x;
    if (idx >= 1179648) return;
    int co = idx / 1152;
    int k  = idx - co * 1152;
    const float* w = (co < 512) ? wfx : wx;
    int c = (co < 512) ? co : co - 512;
    int tap = k / 128, rem = k - tap * 128;
    int grp = rem >> 5, kl = rem & 31;
    int pos = tap * 128 + grp * 32 + (kl & 3) * 8 + (kl >> 2);
    g_wt[(size_t)co * 1152 + pos] = __uint_as_float(cvt_tf32(w[(size_t)k * 512 + c]));
}
__global__ void wprep_x_kernel(const float* __restrict__ x)
{
    int idx = (blockIdx.x * 256 + threadIdx.x) * 4;     // aligned 4, same 32-group
    float4 v = *(const float4*)(x + idx);
    int base = idx & ~31;
    int kl0  = idx & 31;
    float* dst = g_xr + base + (kl0 >> 2);
    dst[0]  = __uint_as_float(cvt_tf32(v.x));
    dst[8]  = __uint_as_float(cvt_tf32(v.y));
    dst[16] = __uint_as_float(cvt_tf32(v.z));
    dst[24] = __uint_as_float(cvt_tf32(v.w));
}

// ---------------- conv: implicit GEMM, tf32 mma, 3-stage, 2 CTAs/SM ---------
// grid (1024 rows, 8 ctiles of 128co), 256 threads, warp tile 64x32.
// k-interleaved fragments: LDS.128 loads, 24 per warp-chunk.
__global__ void __launch_bounds__(256, 2)
conv_mma_kernel(const float* __restrict__ bfx, const float* __restrict__ bx)
{
    extern __shared__ float sm[];
    const int tid  = threadIdx.x;
    const int wid  = tid >> 5;
    const int lane = tid & 31;
    const int g    = lane >> 2;
    const int t4   = lane & 3;
    const int warpM = wid & 1;     // 2 M-groups of 64
    const int warpN = wid >> 1;    // 4 N-groups of 32

    const int row = blockIdx.x;
    const int b   = row >> 7;
    const int y   = row & 127;
    const int ct  = blockIdx.y;          // 0..7 (0-3 fx, 4-7 xm)
    const int co0 = ct * 128;

    float acc[4][4][4] = {};

    auto load_stage = [&](int c, int s) {
        float* base = sm + s * 9216;
        const int tap = c >> 2;
        const int dy = tap / 3 - 1, dx = tap % 3 - 1;
        const int yy = y + dy;
        const bool rowok = (unsigned)yy < 128u;
        const int ci0 = (c & 3) * 32;
        const int k0w = tap * 128 + ci0;
        const float* xb = g_xr + ((size_t)(b * 128 + (rowok ? yy : 0)) * 128) * 128;
        #pragma unroll
        for (int i = 0; i < 4; ++i) {
            int f = tid + 256 * i;
            int r = f >> 3, q = f & 7;
            int xp = r + dx;
            bool ok = rowok && (unsigned)xp < 128u;
            const float* src = xb + (size_t)(ok ? xp : 0) * 128 + ci0 + q * 4;
            CP16Z(smem_u32(base + r * 36 + q * 4), src, ok ? 16 : 0);
        }
        #pragma unroll
        for (int i = 0; i < 4; ++i) {
            int f = tid + 256 * i;
            int r = f >> 3, q = f & 7;
            const float* src = g_wt + (size_t)(co0 + r) * 1152 + k0w + q * 4;
            CP16(smem_u32(base + 4608 + r * 36 + q * 4), src);
        }
    };
    auto compute = [&](int s) {
        const float* As_ = sm + s * 9216;
        const float* Bs_ = As_ + 4608;
        const int m0 = warpM * 64;
        const int n0 = warpN * 32;
        #pragma unroll
        for (int kh = 0; kh < 2; ++kh) {
            const int off = t4 * 8 + kh * 4;
            float4 fa[4][2];
            #pragma unroll
            for (int mt = 0; mt < 4; ++mt) {
                fa[mt][0] = *(const float4*)(As_ + (m0 + mt * 16 + g) * 36 + off);
                fa[mt][1] = *(const float4*)(As_ + (m0 + mt * 16 + 8 + g) * 36 + off);
            }
            #pragma unroll
            for (int nt = 0; nt < 4; ++nt) {
                float4 fb = *(const float4*)(Bs_ + (n0 + nt * 8 + g) * 36 + off);
                unsigned b0[2] = { __float_as_uint(fb.x), __float_as_uint(fb.y) };
                unsigned b1[2] = { __float_as_uint(fb.z), __float_as_uint(fb.w) };
                #pragma unroll
                for (int mt = 0; mt < 4; ++mt) {
                    unsigned a0[4] = { __float_as_uint(fa[mt][0].x),
                                       __float_as_uint(fa[mt][1].x),
                                       __float_as_uint(fa[mt][0].y),
                                       __float_as_uint(fa[mt][1].y) };
                    mma_tf32(acc[mt][nt], a0, b0);
                    unsigned a1[4] = { __float_as_uint(fa[mt][0].z),
                                       __float_as_uint(fa[mt][1].z),
                                       __float_as_uint(fa[mt][0].w),
                                       __float_as_uint(fa[mt][1].w) };
                    mma_tf32(acc[mt][nt], a1, b1);
                }
            }
        }
    };

    load_stage(0, 0); CP_COMMIT();
    load_stage(1, 1); CP_COMMIT();

    for (int c = 0; c < 36; ++c) {
        if (c < 35) { CP_WAIT(1); } else { CP_WAIT(0); }
        __syncthreads();
        if (c + 2 < 36) {
            load_stage(c + 2, (c + 2) % 3);
            CP_COMMIT();
        }
        compute(c % 3);
    }

    if (ct < 4) {
        // fx: transpose in smem, write (B,512co,16384n) coalesced
        __syncthreads();
        float* T = sm;                  // [128 co][132]
        #pragma unroll
        for (int mt = 0; mt < 4; ++mt) {
            const int m = warpM * 64 + mt * 16 + g;
            #pragma unroll
            for (int nt = 0; nt < 4; ++nt) {
                const int nl = warpN * 32 + nt * 8 + t4 * 2;
                T[(size_t)nl * 132 + m]           = acc[mt][nt][0];
                T[(size_t)(nl + 1) * 132 + m]     = acc[mt][nt][1];
                T[(size_t)nl * 132 + m + 8]       = acc[mt][nt][2];
                T[(size_t)(nl + 1) * 132 + m + 8] = acc[mt][nt][3];
            }
        }
        __syncthreads();
        const float* biasp = bfx + ct * 128;
        float* dst = g_fxt + ((size_t)b * 512 + ct * 128) * 16384 + y * 128;
        #pragma unroll 4
        for (int r = 0; r < 16; ++r) {
            int co = wid * 16 + r;
            float bb = __ldg(biasp + co);
            float4 v = *(const float4*)&T[(size_t)co * 132 + lane * 4];
            v.x += bb; v.y += bb; v.z += bb; v.w += bb;
            *(float4*)(dst + (size_t)co * 16384 + lane * 4) = v;
        }
    } else {
        const int cin = (ct - 4) * 128;
        const float* biasp = bx + cin;
        float* outb = g_xm + ((size_t)(b * N_ + y * 128)) * 512 + cin;
        #pragma unroll
        for (int mt = 0; mt < 4; ++mt) {
            const int m = warpM * 64 + mt * 16 + g;
            #pragma unroll
            for (int nt = 0; nt < 4; ++nt) {
                const int nl = warpN * 32 + nt * 8 + t4 * 2;
                float b0 = __ldg(biasp + nl), b1 = __ldg(biasp + nl + 1);
                *(float2*)(outb + (size_t)m * 512 + nl) =
                    make_float2(acc[mt][nt][0] + b0, acc[mt][nt][1] + b1);
                *(float2*)(outb + (size_t)(m + 8) * 512 + nl) =
                    make_float2(acc[mt][nt][2] + b0, acc[mt][nt][3] + b1);
            }
        }
    }
}

// ---------------- slice weights: GEMM + softmax, 256-token tiles -------------
__global__ void __launch_bounds__(256)
sliceweights_kernel(const float* __restrict__ slice_w,
                    const float* __restrict__ slice_b,
                    const float* __restrict__ temperature)
{
    extern __shared__ float dsm[];
    float* Xst = dsm;            // [c][t], stride 260
    float* Wt  = dsm + 16640;    // [c][g], stride 68
    float* NP  = dsm + 20992;    // [warp][g]

    const int tid  = threadIdx.x;
    const int h    = blockIdx.y;
    const int b    = blockIdx.x >> 6;
    const int tile = blockIdx.x & 63;
    const int bn0  = b * N_ + tile * 256;
    const int nin  = tile * 256;

    for (int i = tid; i < 4096; i += 256) {
        int gg = i >> 6, c = i & 63;
        Wt[c * 68 + gg] = slice_w[i];
    }
    #pragma unroll
    for (int i = 0; i < 16; ++i) {
        int f = tid + 256 * i;
        int t = f >> 4, c4 = f & 15;
        float4 v = *(const float4*)(g_xm + (size_t)(bn0 + t) * 512 + h * 64 + c4 * 4);
        Xst[(c4 * 4 + 0) * 260 + t] = v.x;
        Xst[(c4 * 4 + 1) * 260 + t] = v.y;
        Xst[(c4 * 4 + 2) * 260 + t] = v.z;
        Xst[(c4 * 4 + 3) * 260 + t] = v.w;
    }
    __syncthreads();

    const int tx = tid & 7;
    const int ty = tid >> 3;
    const int t0 = ty * 8;
    const int g0 = tx * 8;
    const int lane = tid & 31;
    const int warp = tid >> 5;

    float acc[8][8] = {};
    #pragma unroll 2
    for (int c = 0; c < 64; ++c) {
        float4 a0 = *(const float4*)&Xst[c * 260 + t0];
        float4 a1 = *(const float4*)&Xst[c * 260 + t0 + 4];
        float4 b0 = *(const float4*)&Wt[c * 68 + g0];
        float4 b1 = *(const float4*)&Wt[c * 68 + g0 + 4];
        float av[8] = {a0.x, a0.y, a0.z, a0.w, a1.x, a1.y, a1.z, a1.w};
        #pragma unroll
        for (int i = 0; i < 8; ++i) {
            acc[i][0] += av[i] * b0.x; acc[i][1] += av[i] * b0.y;
            acc[i][2] += av[i] * b0.z; acc[i][3] += av[i] * b0.w;
            acc[i][4] += av[i] * b1.x; acc[i][5] += av[i] * b1.y;
            acc[i][6] += av[i] * b1.z; acc[i][7] += av[i] * b1.w;
        }
    }

    float tv = temperature[h];
    tv = fminf(fmaxf(tv, 0.1f), 5.0f);
    float invt = 1.f / tv;
    float bias[8];
    #pragma unroll
    for (int j = 0; j < 8; ++j) bias[j] = __ldg(slice_b + g0 + j);

    #pragma unroll
    for (int i = 0; i < 8; ++i) {
        float l[8];
        #pragma unroll
        for (int j = 0; j < 8; ++j) l[j] = (acc[i][j] + bias[j]) * invt;
        float mx = l[0];
        #pragma unroll
        for (int j = 1; j < 8; ++j) mx = fmaxf(mx, l[j]);
        #pragma unroll
        for (int o = 1; o < 8; o <<= 1)
            mx = fmaxf(mx, __shfl_xor_sync(0xffffffffu, mx, o));
        float s = 0.f;
        #pragma unroll
        for (int j = 0; j < 8; ++j) { l[j] = __expf(l[j] - mx); s += l[j]; }
        #pragma unroll
        for (int o = 1; o < 8; o <<= 1)
            s += __shfl_xor_sync(0xffffffffu, s, o);
        float inv = 1.f / s;
        #pragma unroll
        for (int j = 0; j < 8; ++j) acc[i][j] = l[j] * inv;
    }

    const int bh = b * 8 + h;
    float* gb = g_swt + (((size_t)bh * 64 + g0) * 16384) + nin + t0;
    #pragma unroll
    for (int j = 0; j < 8; ++j) {
        *(float4*)(gb + (size_t)j * 16384) =
            make_float4(acc[0][j], acc[1][j], acc[2][j], acc[3][j]);
        *(float4*)(gb + (size_t)j * 16384 + 4) =
            make_float4(acc[4][j], acc[5][j], acc[6][j], acc[7][j]);
    }

    float pn[8];
    #pragma unroll
    for (int j = 0; j < 8; ++j) {
        float p = acc[0][j] + acc[1][j] + acc[2][j] + acc[3][j]
                + acc[4][j] + acc[5][j] + acc[6][j] + acc[7][j];
        p += __shfl_xor_sync(0xffffffffu, p, 8);
        p += __shfl_xor_sync(0xffffffffu, p, 16);
        pn[j] = p;
    }
    if (lane < 8) {
        #pragma unroll
        for (int j = 0; j < 8; ++j) NP[warp * 64 + lane * 8 + j] = pn[j];
    }
    __syncthreads();
    if (tid < 64) {
        float s = 0.f;
        #pragma unroll
        for (int wv = 0; wv < 8; ++wv) s += NP[wv * 64 + tid];
        g_npart[((size_t)bh * 64 + tile) * 64 + tid] = s;
    }
}

// ---------------- slice_token: tf32 hi/lo mma GEMM over K=n ------------------
__global__ void __launch_bounds__(256)
slicetoken_kernel()
{
    extern __shared__ float sm2[];
    const int tid  = threadIdx.x;
    const int wid  = tid >> 5;
    const int lane = tid & 31;
    const int g    = lane >> 2;
    const int t4   = lane & 3;
    const int bh   = blockIdx.x;
    const int b    = bh >> 3, h = bh & 7;
    const int n0   = blockIdx.y * 1024;

    const float* arow = g_swt + (size_t)bh * 64 * 16384;
    const float* brow = g_fxt + ((size_t)b * 512 + h * 64) * 16384;

    auto load = [&](int kt, int s) {
        float* base = sm2 + s * 8704;
        const int nn = n0 + kt * 64;
        #pragma unroll
        for (int i = 0; i < 4; ++i) {
            int f = tid + 256 * i;
            int r = f >> 4, q = f & 15;
            CP16(smem_u32(base + r * 68 + q * 4),
                 arow + (size_t)r * 16384 + nn + q * 4);
            CP16(smem_u32(base + 4352 + r * 68 + q * 4),
                 brow + (size_t)r * 16384 + nn + q * 4);
        }
    };

    float acc[4][4] = {};
    const int m0  = (wid & 3) * 16;
    const int nc0 = (wid >> 2) * 32;

    load(0, 0); CP_COMMIT();
    for (int kt = 0; kt < 16; ++kt) {
        CP_WAIT(0);
        __syncthreads();
        if (kt + 1 < 16) { load(kt + 1, (kt + 1) & 1); CP_COMMIT(); }
        const float* As_ = sm2 + (kt & 1) * 8704;
        const float* Bs_ = As_ + 4352;
        #pragma unroll
        for (int ks = 0; ks < 8; ++ks) {
            const int kk = ks * 8;
            unsigned afh[4], afl[4];
            const float* p0 = As_ + (m0 + g) * 68 + kk + t4;
            const float* p1 = p0 + 544;
            split_tf32(p0[0], afh[0], afl[0]);
            split_tf32(p1[0], afh[1], afl[1]);
            split_tf32(p0[4], afh[2], afl[2]);
            split_tf32(p1[4], afh[3], afl[3]);
            #pragma unroll
            for (int nt = 0; nt < 4; ++nt) {
                unsigned bfh[2], bfl[2];
                const float* p = Bs_ + (nc0 + nt * 8 + g) * 68 + kk + t4;
                split_tf32(p[0], bfh[0], bfl[0]);
                split_tf32(p[4], bfh[1], bfl[1]);
                mma_tf32(acc[nt], afh, bfh);
                mma_tf32(acc[nt], afl, bfh);
                mma_tf32(acc[nt], afh, bfl);
            }
        }
    }

    float* p = g_part + ((size_t)blockIdx.y * 64 + bh) * 4096;
    #pragma unroll
    for (int nt = 0; nt < 4; ++nt) {
        const int col = nc0 + nt * 8 + t4 * 2;
        *(float2*)(p + (m0 + g) * 64 + col)     = make_float2(acc[nt][0], acc[nt][1]);
        *(float2*)(p + (m0 + 8 + g) * 64 + col) = make_float2(acc[nt][2], acc[nt][3]);
    }
}

// ---------------- reduce partials --------------------------------------------
__global__ void reduce_token_kernel()
{
    int idx = blockIdx.x * 512 + threadIdx.x;
    float s = 0.f;
    #pragma unroll
    for (int ch = 0; ch < 16; ++ch) s += g_part[(size_t)ch * 262144 + idx];
    g_st[idx] = s;
    if (idx < 4096) {
        int bh = idx >> 6, gg = idx & 63;
        float ns = 0.f;
        for (int t = 0; t < 64; ++t)
            ns += g_npart[((size_t)bh * 64 + t) * 64 + gg];
        g_norm[idx] = ns;
    }
}

// ---------------- normalize + QKV --------------------------------------------
__global__ void qkv_kernel(const float* __restrict__ wq,
                           const float* __restrict__ wk,
                           const float* __restrict__ wv)
{
    __shared__ float S[64][65];
    int bh = blockIdx.x;
    int tid = threadIdx.x;
    const float* st = g_st + (size_t)bh * 4096;
    const float* nm = g_norm + bh * 64;
    for (int i = tid; i < 4096; i += 256)
        S[i >> 6][i & 63] = st[i] / (nm[i >> 6] + 1e-5f);
    __syncthreads();

    int g = tid >> 2;
    int d0 = (tid & 3) * 16;
    for (int d = d0; d < d0 + 16; ++d) {
        float q = 0.f, k = 0.f, v = 0.f;
        #pragma unroll 8
        for (int c = 0; c < 64; ++c) {
            float s = S[g][c];
            q += s * wq[d * 64 + c];
            k += s * wk[d * 64 + c];
            v += s * wv[d * 64 + c];
        }
        int o = bh * 4096 + g * 64 + d;
        g_q[o] = q; g_k[o] = k; g_v[o] = v;
    }
}

// ---------------- 64x64 attention per (b,h) ----------------------------------
__global__ void attn_kernel()
{
    __shared__ float X[64][65];
    __shared__ float Y[64][65];
    int bh = blockIdx.x;
    int tid = threadIdx.x;
    for (int i = tid; i < 4096; i += 256) {
        X[i >> 6][i & 63] = g_q[bh * 4096 + i];
        Y[i >> 6][i & 63] = g_k[bh * 4096 + i];
    }
    __syncthreads();

    int g = tid >> 2;
    int k0 = (tid & 3) * 16;
    float a[16];
    #pragma unroll
    for (int i = 0; i < 16; ++i) {
        float s = 0.f;
        for (int c = 0; c < 64; ++c) s += X[g][c] * Y[k0 + i][c];
        a[i] = s * 0.125f;
    }
    __syncthreads();
    #pragma unroll
    for (int i = 0; i < 16; ++i) X[g][k0 + i] = a[i];
    for (int i = tid; i < 4096; i += 256)
        Y[i >> 6][i & 63] = g_v[bh * 4096 + i];
    __syncthreads();

    if (tid < 64) {
        float mx = -1e30f;
        for (int k = 0; k < 64; ++k) mx = fmaxf(mx, X[tid][k]);
        float s = 0.f;
        for (int k = 0; k < 64; ++k) { float e = __expf(X[tid][k] - mx); X[tid][k] = e; s += e; }
        float inv = 1.f / s;
        for (int k = 0; k < 64; ++k) X[tid][k] *= inv;
    }
    __syncthreads();

    for (int d = k0; d < k0 + 16; ++d) {
        float o = 0.f;
        for (int k = 0; k < 64; ++k) o += X[g][k] * Y[k][d];
        g_os[bh * 4096 + g * 64 + d] = o;
    }
}

// ---------------- OW: fold out_slice through out_w ---------------------------
__global__ void ow_kernel(const float* __restrict__ out_w)
{
    __shared__ float OS[64][65];
    __shared__ float W[64][65];
    const int bh = blockIdx.x;
    const int h  = bh & 7;
    const int tid = threadIdx.x;

    for (int i = tid; i < 4096; i += 256)
        OS[i >> 6][i & 63] = g_os[(size_t)bh * 4096 + i];

    const int ty = tid >> 5;
    const int tx = tid & 31;
    const int dd0 = ty * 8;
    const int gg0 = tx * 2;

    #pragma unroll
    for (int half = 0; half < 2; ++half) {
        const int d0 = half * 64;
        __syncthreads();
        for (int i = tid; i < 4096; i += 256) {
            int dd = i >> 6, c = i & 63;
            W[dd][c] = out_w[(size_t)(d0 + dd) * 512 + h * 64 + c];
        }
        __syncthreads();

        float acc[2][8] = {};
        #pragma unroll 4
        for (int c = 0; c < 64; ++c) {
            float o0 = OS[gg0][c], o1 = OS[gg0 + 1][c];
            #pragma unroll
            for (int dd = 0; dd < 8; ++dd) {
                float wv = W[dd0 + dd][c];
                acc[0][dd] += o0 * wv;
                acc[1][dd] += o1 * wv;
            }
        }
        #pragma unroll
        for (int i = 0; i < 2; ++i) {
            float* dst = g_ow + ((size_t)bh * 64 + gg0 + i) * 128 + d0 + dd0;
            *(float4*)dst = make_float4(acc[i][0], acc[i][1], acc[i][2], acc[i][3]);
            *(float4*)(dst + 4) = make_float4(acc[i][4], acc[i][5], acc[i][6], acc[i][7]);
        }
    }
}

// ---------------- fused final: out = swt^T @ OW + out_b (full 128-d tile) ----
__global__ void final_kernel(const float* __restrict__ out_b,
                             float* __restrict__ out)
{
    __shared__ float As[32][68];
    __shared__ float Bs[32][132];
    const int b     = blockIdx.x >> 8;
    const int m0    = (blockIdx.x & 255) * 64;
    const int tid   = threadIdx.x;
    const int ty = tid >> 4, tx = tid & 15;
    float acc[4][8] = {};

    const float* abase = g_swt + (size_t)b * 512 * 16384;
    const float* bbase = g_ow + (size_t)b * 512 * 128;

    for (int k0 = 0; k0 < 512; k0 += 32) {
        #pragma unroll
        for (int i = 0; i < 2; ++i) {
            int f = tid + 256 * i;
            int r = f >> 4, q = f & 15;
            float4 v = *(const float4*)(abase + (size_t)(k0 + r) * 16384 + m0 + q * 4);
            *(float4*)&As[r][q * 4] = v;
        }
        #pragma unroll
        for (int i = 0; i < 4; ++i) {
            int f = tid + 256 * i;
            int r = f >> 5, q = f & 31;
            float4 v = *(const float4*)(bbase + (size_t)(k0 + r) * 128 + q * 4);
            *(float4*)&Bs[r][q * 4] = v;
        }
        __syncthreads();
        #pragma unroll
        for (int kk = 0; kk < 32; ++kk) {
            float4 a   = *(const float4*)&As[kk][ty * 4];
            float4 bv0 = *(const float4*)&Bs[kk][tx * 4];
            float4 bv1 = *(const float4*)&Bs[kk][64 + tx * 4];
            acc[0][0] += a.x * bv0.x; acc[0][1] += a.x * bv0.y; acc[0][2] += a.x * bv0.z; acc[0][3] += a.x * bv0.w;
            acc[1][0] += a.y * bv0.x; acc[1][1] += a.y * bv0.y; acc[1][2] += a.y * bv0.z; acc[1][3] += a.y * bv0.w;
            acc[2][0] += a.z * bv0.x; acc[2][1] += a.z * bv0.y; acc[2][2] += a.z * bv0.z; acc[2][3] += a.z * bv0.w;
            acc[3][0] += a.w * bv0.x; acc[3][1] += a.w * bv0.y; acc[3][2] += a.w * bv0.z; acc[3][3] += a.w * bv0.w;
            acc[0][4] += a.x * bv1.x; acc[0][5] += a.x * bv1.y; acc[0][6] += a.x * bv1.z; acc[0][7] += a.x * bv1.w;
            acc[1][4] += a.y * bv1.x; acc[1][5] += a.y * bv1.y; acc[1][6] += a.y * bv1.z; acc[1][7] += a.y * bv1.w;
            acc[2][4] += a.z * bv1.x; acc[2][5] += a.z * bv1.y; acc[2][6] += a.z * bv1.z; acc[2][7] += a.z * bv1.w;
            acc[3][4] += a.w * bv1.x; acc[3][5] += a.w * bv1.y; acc[3][6] += a.w * bv1.z; acc[3][7] += a.w * bv1.w;
        }
        __syncthreads();
    }
    #pragma unroll
    for (int i = 0; i < 4; ++i) {
        int n = m0 + ty * 4 + i;
        float* o = out + ((size_t)(b * N_ + n)) * 128;
        #pragma unroll
        for (int j = 0; j < 4; ++j) {
            o[tx * 4 + j]      = acc[i][j]     + __ldg(out_b + tx * 4 + j);
            o[64 + tx * 4 + j] = acc[i][4 + j] + __ldg(out_b + 64 + tx * 4 + j);
        }
    }
}

// ---------------- launch ------------------------------------------------------
extern "C" void kernel_launch(void* const* d_in, const int* in_sizes, int n_in,
                              void* d_out, int out_size)
{
    const float* x          = (const float*)d_in[0];
    const float* conv_fx_w  = (const float*)d_in[1];
    const float* conv_fx_b  = (const float*)d_in[2];
    const float* conv_x_w   = (const float*)d_in[3];
    const float* conv_x_b   = (const float*)d_in[4];
    const float* slice_w    = (const float*)d_in[5];
    const float* slice_b    = (const float*)d_in[6];
    const float* temperature= (const float*)d_in[7];
    const float* wq         = (const float*)d_in[8];
    const float* wk         = (const float*)d_in[9];
    const float* wv         = (const float*)d_in[10];
    const float* out_w      = (const float*)d_in[11];
    const float* out_b      = (const float*)d_in[12];
    float* out = (float*)d_out;

    cudaFuncSetAttribute(conv_mma_kernel,
                         cudaFuncAttributeMaxDynamicSharedMemorySize, 110592);
    cudaFuncSetAttribute(sliceweights_kernel,
                         cudaFuncAttributeMaxDynamicSharedMemorySize, 86016);
    cudaFuncSetAttribute(slicetoken_kernel,
                         cudaFuncAttributeMaxDynamicSharedMemorySize, 69632);

    wprep_kernel<<<4608, 256>>>(conv_fx_w, conv_x_w);
    wprep_x_kernel<<<16384, 256>>>(x);
    conv_mma_kernel<<<dim3(1024, 8), 256, 110592>>>(conv_fx_b, conv_x_b);
    sliceweights_kernel<<<dim3(512, 8), 256, 86016>>>(slice_w, slice_b, temperature);
    slicetoken_kernel<<<dim3(64, 16), 256, 69632>>>();
    reduce_token_kernel<<<512, 512>>>();
    qkv_kernel<<<64, 256>>>(wq, wk, wv);
    attn_kernel<<<64, 256>>>();
    ow_kernel<<<64, 256>>>(out_w);
    final_kernel<<<2048, 256>>>(out_b, out);
}

// round 13
// speedup vs baseline: 1.1265x; 1.1265x over previous
#include <cuda_runtime.h>

#define B_     8
#define N_     16384
#define DIM_   128

// ---------------- scratch (device globals) ----------------------------------
__device__ float g_xr[16777216];   // tf32-rounded x (B,N,128)
__device__ float g_fxt[67108864];  // conv_fx TRANSPOSED (B,512co,16384n)
__device__ float g_xm[67108864];   // conv_x output (B,N,512)
__device__ float g_swt[67108864];  // slice weights TRANSPOSED (B,H,64g,16384n)
__device__ float g_part[4194304];  // 16 chunks x 64 bh x 4096
__device__ float g_npart[262144];  // 64 bh x 64 tiles x 64 g
__device__ float g_st[262144];
__device__ float g_norm[4096];
__device__ float g_q[262144];
__device__ float g_k[262144];
__device__ float g_v[262144];
__device__ float g_os[262144];
__device__ float g_ow[524288];     // OW (B, 512k, 128d)
__device__ float g_wt[1179648];    // tf32 weights [1024 co][1152 k]

__device__ __forceinline__ unsigned cvt_tf32(float f) {
    unsigned u;
    asm("cvt.rna.tf32.f32 %0, %1;" : "=r"(u) : "f"(f));
    return u;
}
__device__ __forceinline__ void split_tf32(float v, unsigned& hi, unsigned& lo) {
    hi = cvt_tf32(v);
    lo = cvt_tf32(v - __uint_as_float(hi));
}
__device__ __forceinline__ unsigned smem_u32(const void* p) {
    unsigned a;
    asm("{ .reg .u64 t; cvta.to.shared.u64 t, %1; cvt.u32.u64 %0, t; }"
        : "=r"(a) : "l"(p));
    return a;
}
__device__ __forceinline__ void mma_tf32(float* c, const unsigned* a, const unsigned* b) {
    asm volatile("mma.sync.aligned.m16n8k8.row.col.f32.tf32.tf32.f32 "
                 "{%0,%1,%2,%3}, {%4,%5,%6,%7}, {%8,%9}, {%0,%1,%2,%3};"
                 : "+f"(c[0]), "+f"(c[1]), "+f"(c[2]), "+f"(c[3])
                 : "r"(a[0]), "r"(a[1]), "r"(a[2]), "r"(a[3]),
                   "r"(b[0]), "r"(b[1]));
}
#define CP16(dst, src) \
    asm volatile("cp.async.cg.shared.global [%0], [%1], 16;" :: "r"(dst), "l"(src))
#define CP16Z(dst, src, sz) \
    asm volatile("cp.async.cg.shared.global [%0], [%1], 16, %2;" :: "r"(dst), "l"(src), "r"(sz))
#define CP_COMMIT() asm volatile("cp.async.commit_group;")
#define CP_WAIT(n)  asm volatile("cp.async.wait_group %0;" :: "n"(n))

// ---------------- prep: weights + x tf32 rounding ---------------------------
__global__ void wprep_kernel(const float* __restrict__ wfx,
                             const float* __restrict__ wx)
{
    int idx = blockIdx.x * 256 + threadIdx.x;
    if (idx >= 1179648) return;
    int co = idx / 1152;
    int k  = idx - co * 1152;
    const float* w = (co < 512) ? wfx : wx;
    int c = (co < 512) ? co : co - 512;
    g_wt[idx] = __uint_as_float(cvt_tf32(w[(size_t)k * 512 + c]));
}
__global__ void wprep_x_kernel(const float* __restrict__ x)
{
    int idx = (blockIdx.x * 256 + threadIdx.x) * 4;
    float4 v = *(const float4*)(x + idx);
    uint4 u;
    u.x = cvt_tf32(v.x); u.y = cvt_tf32(v.y);
    u.z = cvt_tf32(v.z); u.w = cvt_tf32(v.w);
    *(uint4*)(g_xr + idx) = u;
}

// ---------------- conv: implicit GEMM, tf32 mma, 3-stage, 2 CTAs/SM ---------
// grid (1024 rows, 8 ctiles of 128co), 256 threads, warp tile 64x32.
// Stage = A 128x36 (18KB) + B 128x36 (18KB); 3 stages = 108KB -> 2 CTAs/SM.
__global__ void __launch_bounds__(256, 2)
conv_mma_kernel(const float* __restrict__ bfx, const float* __restrict__ bx)
{
    extern __shared__ float sm[];
    const int tid  = threadIdx.x;
    const int wid  = tid >> 5;
    const int lane = tid & 31;
    const int g    = lane >> 2;
    const int t4   = lane & 3;
    const int warpM = wid & 1;     // 2 M-groups of 64
    const int warpN = wid >> 1;    // 4 N-groups of 32

    const int row = blockIdx.x;
    const int b   = row >> 7;
    const int y   = row & 127;
    const int ct  = blockIdx.y;          // 0..7 (0-3 fx, 4-7 xm)
    const int co0 = ct * 128;

    float acc[4][4][4] = {};

    auto load_stage = [&](int c, int s) {
        float* base = sm + s * 9216;
        const int tap = c >> 2;
        const int dy = tap / 3 - 1, dx = tap % 3 - 1;
        const int yy = y + dy;
        const bool rowok = (unsigned)yy < 128u;
        const int ci0 = (c & 3) * 32;
        const int k0w = tap * 128 + ci0;
        const float* xb = g_xr + ((size_t)(b * 128 + (rowok ? yy : 0)) * 128) * 128;
        #pragma unroll
        for (int i = 0; i < 4; ++i) {
            int f = tid + 256 * i;
            int r = f >> 3, q = f & 7;
            int xp = r + dx;
            bool ok = rowok && (unsigned)xp < 128u;
            const float* src = xb + (size_t)(ok ? xp : 0) * 128 + ci0 + q * 4;
            CP16Z(smem_u32(base + r * 36 + q * 4), src, ok ? 16 : 0);
        }
        #pragma unroll
        for (int i = 0; i < 4; ++i) {
            int f = tid + 256 * i;
            int r = f >> 3, q = f & 7;
            const float* src = g_wt + (size_t)(co0 + r) * 1152 + k0w + q * 4;
            CP16(smem_u32(base + 4608 + r * 36 + q * 4), src);
        }
    };
    auto compute = [&](int s) {
        const float* As_ = sm + s * 9216;
        const float* Bs_ = As_ + 4608;
        const int m0 = warpM * 64;
        const int n0 = warpN * 32;
        #pragma unroll
        for (int ks = 0; ks < 4; ++ks) {
            const int kk = ks * 8;
            unsigned af[4][4];
            #pragma unroll
            for (int mt = 0; mt < 4; ++mt) {
                const float* p0 = As_ + (m0 + mt * 16 + g) * 36 + kk + t4;
                const float* p1 = p0 + 288;
                af[mt][0] = __float_as_uint(p0[0]);
                af[mt][1] = __float_as_uint(p1[0]);
                af[mt][2] = __float_as_uint(p0[4]);
                af[mt][3] = __float_as_uint(p1[4]);
            }
            unsigned bf[4][2];
            #pragma unroll
            for (int nt = 0; nt < 4; ++nt) {
                const float* p = Bs_ + (n0 + nt * 8 + g) * 36 + kk + t4;
                bf[nt][0] = __float_as_uint(p[0]);
                bf[nt][1] = __float_as_uint(p[4]);
            }
            #pragma unroll
            for (int mt = 0; mt < 4; ++mt)
                #pragma unroll
                for (int nt = 0; nt < 4; ++nt)
                    mma_tf32(acc[mt][nt], af[mt], bf[nt]);
        }
    };

    load_stage(0, 0); CP_COMMIT();
    load_stage(1, 1); CP_COMMIT();

    for (int c = 0; c < 36; ++c) {
        if (c < 35) { CP_WAIT(1); } else { CP_WAIT(0); }
        __syncthreads();
        if (c + 2 < 36) {
            load_stage(c + 2, (c + 2) % 3);
            CP_COMMIT();
        }
        compute(c % 3);
    }

    if (ct < 4) {
        // fx: transpose in smem, write (B,512co,16384n) coalesced
        __syncthreads();
        float* T = sm;                  // [128 co][132]
        #pragma unroll
        for (int mt = 0; mt < 4; ++mt) {
            const int m = warpM * 64 + mt * 16 + g;
            #pragma unroll
            for (int nt = 0; nt < 4; ++nt) {
                const int nl = warpN * 32 + nt * 8 + t4 * 2;
                T[(size_t)nl * 132 + m]           = acc[mt][nt][0];
                T[(size_t)(nl + 1) * 132 + m]     = acc[mt][nt][1];
                T[(size_t)nl * 132 + m + 8]       = acc[mt][nt][2];
                T[(size_t)(nl + 1) * 132 + m + 8] = acc[mt][nt][3];
            }
        }
        __syncthreads();
        const float* biasp = bfx + ct * 128;
        float* dst = g_fxt + ((size_t)b * 512 + ct * 128) * 16384 + y * 128;
        #pragma unroll 4
        for (int r = 0; r < 16; ++r) {
            int co = wid * 16 + r;
            float bb = __ldg(biasp + co);
            float4 v = *(const float4*)&T[(size_t)co * 132 + lane * 4];
            v.x += bb; v.y += bb; v.z += bb; v.w += bb;
            *(float4*)(dst + (size_t)co * 16384 + lane * 4) = v;
        }
    } else {
        const int cin = (ct - 4) * 128;
        const float* biasp = bx + cin;
        float* outb = g_xm + ((size_t)(b * N_ + y * 128)) * 512 + cin;
        #pragma unroll
        for (int mt = 0; mt < 4; ++mt) {
            const int m = warpM * 64 + mt * 16 + g;
            #pragma unroll
            for (int nt = 0; nt < 4; ++nt) {
                const int nl = warpN * 32 + nt * 8 + t4 * 2;
                float b0 = __ldg(biasp + nl), b1 = __ldg(biasp + nl + 1);
                *(float2*)(outb + (size_t)m * 512 + nl) =
                    make_float2(acc[mt][nt][0] + b0, acc[mt][nt][1] + b1);
                *(float2*)(outb + (size_t)(m + 8) * 512 + nl) =
                    make_float2(acc[mt][nt][2] + b0, acc[mt][nt][3] + b1);
            }
        }
    }
}

// ---------------- slice weights: GEMM + softmax, 256-token tiles -------------
__global__ void __launch_bounds__(256)
sliceweights_kernel(const float* __restrict__ slice_w,
                    const float* __restrict__ slice_b,
                    const float* __restrict__ temperature)
{
    extern __shared__ float dsm[];
    float* Xst = dsm;            // [c][t], stride 260
    float* Wt  = dsm + 16640;    // [c][g], stride 68
    float* NP  = dsm + 20992;    // [warp][g]

    const int tid  = threadIdx.x;
    const int h    = blockIdx.y;
    const int b    = blockIdx.x >> 6;
    const int tile = blockIdx.x & 63;
    const int bn0  = b * N_ + tile * 256;
    const int nin  = tile * 256;

    for (int i = tid; i < 4096; i += 256) {
        int gg = i >> 6, c = i & 63;
        Wt[c * 68 + gg] = slice_w[i];
    }
    #pragma unroll
    for (int i = 0; i < 16; ++i) {
        int f = tid + 256 * i;
        int t = f >> 4, c4 = f & 15;
        float4 v = *(const float4*)(g_xm + (size_t)(bn0 + t) * 512 + h * 64 + c4 * 4);
        Xst[(c4 * 4 + 0) * 260 + t] = v.x;
        Xst[(c4 * 4 + 1) * 260 + t] = v.y;
        Xst[(c4 * 4 + 2) * 260 + t] = v.z;
        Xst[(c4 * 4 + 3) * 260 + t] = v.w;
    }
    __syncthreads();

    const int tx = tid & 7;
    const int ty = tid >> 3;
    const int t0 = ty * 8;
    const int g0 = tx * 8;
    const int lane = tid & 31;
    const int warp = tid >> 5;

    float acc[8][8] = {};
    #pragma unroll 2
    for (int c = 0; c < 64; ++c) {
        float4 a0 = *(const float4*)&Xst[c * 260 + t0];
        float4 a1 = *(const float4*)&Xst[c * 260 + t0 + 4];
        float4 b0 = *(const float4*)&Wt[c * 68 + g0];
        float4 b1 = *(const float4*)&Wt[c * 68 + g0 + 4];
        float av[8] = {a0.x, a0.y, a0.z, a0.w, a1.x, a1.y, a1.z, a1.w};
        #pragma unroll
        for (int i = 0; i < 8; ++i) {
            acc[i][0] += av[i] * b0.x; acc[i][1] += av[i] * b0.y;
            acc[i][2] += av[i] * b0.z; acc[i][3] += av[i] * b0.w;
            acc[i][4] += av[i] * b1.x; acc[i][5] += av[i] * b1.y;
            acc[i][6] += av[i] * b1.z; acc[i][7] += av[i] * b1.w;
        }
    }

    float tv = temperature[h];
    tv = fminf(fmaxf(tv, 0.1f), 5.0f);
    float invt = 1.f / tv;
    float bias[8];
    #pragma unroll
    for (int j = 0; j < 8; ++j) bias[j] = __ldg(slice_b + g0 + j);

    #pragma unroll
    for (int i = 0; i < 8; ++i) {
        float l[8];
        #pragma unroll
        for (int j = 0; j < 8; ++j) l[j] = (acc[i][j] + bias[j]) * invt;
        float mx = l[0];
        #pragma unroll
        for (int j = 1; j < 8; ++j) mx = fmaxf(mx, l[j]);
        #pragma unroll
        for (int o = 1; o < 8; o <<= 1)
            mx = fmaxf(mx, __shfl_xor_sync(0xffffffffu, mx, o));
        float s = 0.f;
        #pragma unroll
        for (int j = 0; j < 8; ++j) { l[j] = __expf(l[j] - mx); s += l[j]; }
        #pragma unroll
        for (int o = 1; o < 8; o <<= 1)
            s += __shfl_xor_sync(0xffffffffu, s, o);
        float inv = 1.f / s;
        #pragma unroll
        for (int j = 0; j < 8; ++j) acc[i][j] = l[j] * inv;
    }

    const int bh = b * 8 + h;
    float* gb = g_swt + (((size_t)bh * 64 + g0) * 16384) + nin + t0;
    #pragma unroll
    for (int j = 0; j < 8; ++j) {
        *(float4*)(gb + (size_t)j * 16384) =
            make_float4(acc[0][j], acc[1][j], acc[2][j], acc[3][j]);
        *(float4*)(gb + (size_t)j * 16384 + 4) =
            make_float4(acc[4][j], acc[5][j], acc[6][j], acc[7][j]);
    }

    float pn[8];
    #pragma unroll
    for (int j = 0; j < 8; ++j) {
        float p = acc[0][j] + acc[1][j] + acc[2][j] + acc[3][j]
                + acc[4][j] + acc[5][j] + acc[6][j] + acc[7][j];
        p += __shfl_xor_sync(0xffffffffu, p, 8);
        p += __shfl_xor_sync(0xffffffffu, p, 16);
        pn[j] = p;
    }
    if (lane < 8) {
        #pragma unroll
        for (int j = 0; j < 8; ++j) NP[warp * 64 + lane * 8 + j] = pn[j];
    }
    __syncthreads();
    if (tid < 64) {
        float s = 0.f;
        #pragma unroll
        for (int wv = 0; wv < 8; ++wv) s += NP[wv * 64 + tid];
        g_npart[((size_t)bh * 64 + tile) * 64 + tid] = s;
    }
}

// ---------------- slice_token: tf32 hi/lo mma GEMM over K=n ------------------
__global__ void __launch_bounds__(256)
slicetoken_kernel()
{
    extern __shared__ float sm2[];
    const int tid  = threadIdx.x;
    const int wid  = tid >> 5;
    const int lane = tid & 31;
    const int g    = lane >> 2;
    const int t4   = lane & 3;
    const int bh   = blockIdx.x;
    const int b    = bh >> 3, h = bh & 7;
    const int n0   = blockIdx.y * 1024;

    const float* arow = g_swt + (size_t)bh * 64 * 16384;
    const float* brow = g_fxt + ((size_t)b * 512 + h * 64) * 16384;

    auto load = [&](int kt, int s) {
        float* base = sm2 + s * 8704;
        const int nn = n0 + kt * 64;
        #pragma unroll
        for (int i = 0; i < 4; ++i) {
            int f = tid + 256 * i;
            int r = f >> 4, q = f & 15;
            CP16(smem_u32(base + r * 68 + q * 4),
                 arow + (size_t)r * 16384 + nn + q * 4);
            CP16(smem_u32(base + 4352 + r * 68 + q * 4),
                 brow + (size_t)r * 16384 + nn + q * 4);
        }
    };

    float acc[4][4] = {};
    const int m0  = (wid & 3) * 16;
    const int nc0 = (wid >> 2) * 32;

    load(0, 0); CP_COMMIT();
    for (int kt = 0; kt < 16; ++kt) {
        CP_WAIT(0);
        __syncthreads();
        if (kt + 1 < 16) { load(kt + 1, (kt + 1) & 1); CP_COMMIT(); }
        const float* As_ = sm2 + (kt & 1) * 8704;
        const float* Bs_ = As_ + 4352;
        #pragma unroll
        for (int ks = 0; ks < 8; ++ks) {
            const int kk = ks * 8;
            unsigned afh[4], afl[4];
            const float* p0 = As_ + (m0 + g) * 68 + kk + t4;
            const float* p1 = p0 + 544;
            split_tf32(p0[0], afh[0], afl[0]);
            split_tf32(p1[0], afh[1], afl[1]);
            split_tf32(p0[4], afh[2], afl[2]);
            split_tf32(p1[4], afh[3], afl[3]);
            #pragma unroll
            for (int nt = 0; nt < 4; ++nt) {
                unsigned bfh[2], bfl[2];
                const float* p = Bs_ + (nc0 + nt * 8 + g) * 68 + kk + t4;
                split_tf32(p[0], bfh[0], bfl[0]);
                split_tf32(p[4], bfh[1], bfl[1]);
                mma_tf32(acc[nt], afh, bfh);
                mma_tf32(acc[nt], afl, bfh);
                mma_tf32(acc[nt], afh, bfl);
            }
        }
    }

    float* p = g_part + ((size_t)blockIdx.y * 64 + bh) * 4096;
    #pragma unroll
    for (int nt = 0; nt < 4; ++nt) {
        const int col = nc0 + nt * 8 + t4 * 2;
        *(float2*)(p + (m0 + g) * 64 + col)     = make_float2(acc[nt][0], acc[nt][1]);
        *(float2*)(p + (m0 + 8 + g) * 64 + col) = make_float2(acc[nt][2], acc[nt][3]);
    }
}

// ---------------- reduce partials --------------------------------------------
__global__ void reduce_token_kernel()
{
    int idx = blockIdx.x * 512 + threadIdx.x;
    float s = 0.f;
    #pragma unroll
    for (int ch = 0; ch < 16; ++ch) s += g_part[(size_t)ch * 262144 + idx];
    g_st[idx] = s;
    if (idx < 4096) {
        int bh = idx >> 6, gg = idx & 63;
        float ns = 0.f;
        for (int t = 0; t < 64; ++t)
            ns += g_npart[((size_t)bh * 64 + t) * 64 + gg];
        g_norm[idx] = ns;
    }
}

// ---------------- normalize + QKV --------------------------------------------
__global__ void qkv_kernel(const float* __restrict__ wq,
                           const float* __restrict__ wk,
                           const float* __restrict__ wv)
{
    __shared__ float S[64][65];
    int bh = blockIdx.x;
    int tid = threadIdx.x;
    const float* st = g_st + (size_t)bh * 4096;
    const float* nm = g_norm + bh * 64;
    for (int i = tid; i < 4096; i += 256)
        S[i >> 6][i & 63] = st[i] / (nm[i >> 6] + 1e-5f);
    __syncthreads();

    int g = tid >> 2;
    int d0 = (tid & 3) * 16;
    for (int d = d0; d < d0 + 16; ++d) {
        float q = 0.f, k = 0.f, v = 0.f;
        #pragma unroll 8
        for (int c = 0; c < 64; ++c) {
            float s = S[g][c];
            q += s * wq[d * 64 + c];
            k += s * wk[d * 64 + c];
            v += s * wv[d * 64 + c];
        }
        int o = bh * 4096 + g * 64 + d;
        g_q[o] = q; g_k[o] = k; g_v[o] = v;
    }
}

// ---------------- 64x64 attention per (b,h) ----------------------------------
__global__ void attn_kernel()
{
    __shared__ float X[64][65];
    __shared__ float Y[64][65];
    int bh = blockIdx.x;
    int tid = threadIdx.x;
    for (int i = tid; i < 4096; i += 256) {
        X[i >> 6][i & 63] = g_q[bh * 4096 + i];
        Y[i >> 6][i & 63] = g_k[bh * 4096 + i];
    }
    __syncthreads();

    int g = tid >> 2;
    int k0 = (tid & 3) * 16;
    float a[16];
    #pragma unroll
    for (int i = 0; i < 16; ++i) {
        float s = 0.f;
        for (int c = 0; c < 64; ++c) s += X[g][c] * Y[k0 + i][c];
        a[i] = s * 0.125f;
    }
    __syncthreads();
    #pragma unroll
    for (int i = 0; i < 16; ++i) X[g][k0 + i] = a[i];
    for (int i = tid; i < 4096; i += 256)
        Y[i >> 6][i & 63] = g_v[bh * 4096 + i];
    __syncthreads();

    if (tid < 64) {
        float mx = -1e30f;
        for (int k = 0; k < 64; ++k) mx = fmaxf(mx, X[tid][k]);
        float s = 0.f;
        for (int k = 0; k < 64; ++k) { float e = __expf(X[tid][k] - mx); X[tid][k] = e; s += e; }
        float inv = 1.f / s;
        for (int k = 0; k < 64; ++k) X[tid][k] *= inv;
    }
    __syncthreads();

    for (int d = k0; d < k0 + 16; ++d) {
        float o = 0.f;
        for (int k = 0; k < 64; ++k) o += X[g][k] * Y[k][d];
        g_os[bh * 4096 + g * 64 + d] = o;
    }
}

// ---------------- OW: fold out_slice through out_w ---------------------------
__global__ void ow_kernel(const float* __restrict__ out_w)
{
    __shared__ float OS[64][65];
    __shared__ float W[64][65];
    const int bh = blockIdx.x;
    const int h  = bh & 7;
    const int tid = threadIdx.x;

    for (int i = tid; i < 4096; i += 256)
        OS[i >> 6][i & 63] = g_os[(size_t)bh * 4096 + i];

    const int ty = tid >> 5;
    const int tx = tid & 31;
    const int dd0 = ty * 8;
    const int gg0 = tx * 2;

    #pragma unroll
    for (int half = 0; half < 2; ++half) {
        const int d0 = half * 64;
        __syncthreads();
        for (int i = tid; i < 4096; i += 256) {
            int dd = i >> 6, c = i & 63;
            W[dd][c] = out_w[(size_t)(d0 + dd) * 512 + h * 64 + c];
        }
        __syncthreads();

        float acc[2][8] = {};
        #pragma unroll 4
        for (int c = 0; c < 64; ++c) {
            float o0 = OS[gg0][c], o1 = OS[gg0 + 1][c];
            #pragma unroll
            for (int dd = 0; dd < 8; ++dd) {
                float wv = W[dd0 + dd][c];
                acc[0][dd] += o0 * wv;
                acc[1][dd] += o1 * wv;
            }
        }
        #pragma unroll
        for (int i = 0; i < 2; ++i) {
            float* dst = g_ow + ((size_t)bh * 64 + gg0 + i) * 128 + d0 + dd0;
            *(float4*)dst = make_float4(acc[i][0], acc[i][1], acc[i][2], acc[i][3]);
            *(float4*)(dst + 4) = make_float4(acc[i][4], acc[i][5], acc[i][6], acc[i][7]);
        }
    }
}

// ---------------- fused final: out = swt^T @ OW + out_b (full 128-d tile) ----
__global__ void final_kernel(const float* __restrict__ out_b,
                             float* __restrict__ out)
{
    __shared__ float As[32][68];
    __shared__ float Bs[32][132];
    const int b     = blockIdx.x >> 8;
    const int m0    = (blockIdx.x & 255) * 64;
    const int tid   = threadIdx.x;
    const int ty = tid >> 4, tx = tid & 15;
    float acc[4][8] = {};

    const float* abase = g_swt + (size_t)b * 512 * 16384;
    const float* bbase = g_ow + (size_t)b * 512 * 128;

    for (int k0 = 0; k0 < 512; k0 += 32) {
        #pragma unroll
        for (int i = 0; i < 2; ++i) {
            int f = tid + 256 * i;
            int r = f >> 4, q = f & 15;
            float4 v = *(const float4*)(abase + (size_t)(k0 + r) * 16384 + m0 + q * 4);
            *(float4*)&As[r][q * 4] = v;
        }
        #pragma unroll
        for (int i = 0; i < 4; ++i) {
            int f = tid + 256 * i;
            int r = f >> 5, q = f & 31;
            float4 v = *(const float4*)(bbase + (size_t)(k0 + r) * 128 + q * 4);
            *(float4*)&Bs[r][q * 4] = v;
        }
        __syncthreads();
        #pragma unroll
        for (int kk = 0; kk < 32; ++kk) {
            float4 a   = *(const float4*)&As[kk][ty * 4];
            float4 bv0 = *(const float4*)&Bs[kk][tx * 4];
            float4 bv1 = *(const float4*)&Bs[kk][64 + tx * 4];
            acc[0][0] += a.x * bv0.x; acc[0][1] += a.x * bv0.y; acc[0][2] += a.x * bv0.z; acc[0][3] += a.x * bv0.w;
            acc[1][0] += a.y * bv0.x; acc[1][1] += a.y * bv0.y; acc[1][2] += a.y * bv0.z; acc[1][3] += a.y * bv0.w;
            acc[2][0] += a.z * bv0.x; acc[2][1] += a.z * bv0.y; acc[2][2] += a.z * bv0.z; acc[2][3] += a.z * bv0.w;
            acc[3][0] += a.w * bv0.x; acc[3][1] += a.w * bv0.y; acc[3][2] += a.w * bv0.z; acc[3][3] += a.w * bv0.w;
            acc[0][4] += a.x * bv1.x; acc[0][5] += a.x * bv1.y; acc[0][6] += a.x * bv1.z; acc[0][7] += a.x * bv1.w;
            acc[1][4] += a.y * bv1.x; acc[1][5] += a.y * bv1.y; acc[1][6] += a.y * bv1.z; acc[1][7] += a.y * bv1.w;
            acc[2][4] += a.z * bv1.x; acc[2][5] += a.z * bv1.y; acc[2][6] += a.z * bv1.z; acc[2][7] += a.z * bv1.w;
            acc[3][4] += a.w * bv1.x; acc[3][5] += a.w * bv1.y; acc[3][6] += a.w * bv1.z; acc[3][7] += a.w * bv1.w;
        }
        __syncthreads();
    }
    #pragma unroll
    for (int i = 0; i < 4; ++i) {
        int n = m0 + ty * 4 + i;
        float* o = out + ((size_t)(b * N_ + n)) * 128;
        #pragma unroll
        for (int j = 0; j < 4; ++j) {
            o[tx * 4 + j]      = acc[i][j]     + __ldg(out_b + tx * 4 + j);
            o[64 + tx * 4 + j] = acc[i][4 + j] + __ldg(out_b + 64 + tx * 4 + j);
        }
    }
}

// ---------------- launch ------------------------------------------------------
extern "C" void kernel_launch(void* const* d_in, const int* in_sizes, int n_in,
                              void* d_out, int out_size)
{
    const float* x          = (const float*)d_in[0];
    const float* conv_fx_w  = (const float*)d_in[1];
    const float* conv_fx_b  = (const float*)d_in[2];
    const float* conv_x_w   = (const float*)d_in[3];
    const float* conv_x_b   = (const float*)d_in[4];
    const float* slice_w    = (const float*)d_in[5];
    const float* slice_b    = (const float*)d_in[6];
    const float* temperature= (const float*)d_in[7];
    const float* wq         = (const float*)d_in[8];
    const float* wk         = (const float*)d_in[9];
    const float* wv         = (const float*)d_in[10];
    const float* out_w      = (const float*)d_in[11];
    const float* out_b      = (const float*)d_in[12];
    float* out = (float*)d_out;

    cudaFuncSetAttribute(conv_mma_kernel,
                         cudaFuncAttributeMaxDynamicSharedMemorySize, 110592);
    cudaFuncSetAttribute(sliceweights_kernel,
                         cudaFuncAttributeMaxDynamicSharedMemorySize, 86016);
    cudaFuncSetAttribute(slicetoken_kernel,
                         cudaFuncAttributeMaxDynamicSharedMemorySize, 69632);

    wprep_kernel<<<4608, 256>>>(conv_fx_w, conv_x_w);
    wprep_x_kernel<<<16384, 256>>>(x);
    conv_mma_kernel<<<dim3(1024, 8), 256, 110592>>>(conv_fx_b, conv_x_b);
    sliceweights_kernel<<<dim3(512, 8), 256, 86016>>>(slice_w, slice_b, temperature);
    slicetoken_kernel<<<dim3(64, 16), 256, 69632>>>();
    reduce_token_kernel<<<512, 512>>>();
    qkv_kernel<<<64, 256>>>(wq, wk, wv);
    attn_kernel<<<64, 256>>>();
    ow_kernel<<<64, 256>>>(out_w);
    final_kernel<<<2048, 256>>>(out_b, out);
}

// round 14
// speedup vs baseline: 1.1865x; 1.0533x over previous
#include <cuda_runtime.h>

#define B_     8
#define N_     16384
#define DIM_   128

// ---------------- scratch (device globals) ----------------------------------
__device__ float g_xr[16777216];   // tf32-rounded x (B,N,128)
__device__ float g_fxt[67108864];  // conv_fx TRANSPOSED (B,512co,16384n)
__device__ float g_xm[67108864];   // conv_x output (B,N,512)
__device__ float g_swt[67108864];  // slice weights TRANSPOSED (B,H,64g,16384n)
__device__ float g_part[4194304];  // 16 chunks x 64 bh x 4096
__device__ float g_npart[262144];  // 64 bh x 64 tiles x 64 g
__device__ float g_st[262144];
__device__ float g_norm[4096];
__device__ float g_q[262144];
__device__ float g_k[262144];
__device__ float g_v[262144];
__device__ float g_os[262144];
__device__ float g_ow[524288];     // OW (B, 512k, 128d)
__device__ float g_wt[1179648];    // tf32 weights [1024 co][1152 k]

__device__ __forceinline__ unsigned cvt_tf32(float f) {
    unsigned u;
    asm("cvt.rna.tf32.f32 %0, %1;" : "=r"(u) : "f"(f));
    return u;
}
__device__ __forceinline__ void split_tf32(float v, unsigned& hi, unsigned& lo) {
    hi = cvt_tf32(v);
    lo = cvt_tf32(v - __uint_as_float(hi));
}
__device__ __forceinline__ unsigned smem_u32(const void* p) {
    unsigned a;
    asm("{ .reg .u64 t; cvta.to.shared.u64 t, %1; cvt.u32.u64 %0, t; }"
        : "=r"(a) : "l"(p));
    return a;
}
__device__ __forceinline__ void mma_tf32(float* c, const unsigned* a, const unsigned* b) {
    asm volatile("mma.sync.aligned.m16n8k8.row.col.f32.tf32.tf32.f32 "
                 "{%0,%1,%2,%3}, {%4,%5,%6,%7}, {%8,%9}, {%0,%1,%2,%3};"
                 : "+f"(c[0]), "+f"(c[1]), "+f"(c[2]), "+f"(c[3])
                 : "r"(a[0]), "r"(a[1]), "r"(a[2]), "r"(a[3]),
                   "r"(b[0]), "r"(b[1]));
}
#define CP16(dst, src) \
    asm volatile("cp.async.cg.shared.global [%0], [%1], 16;" :: "r"(dst), "l"(src))
#define CP16Z(dst, src, sz) \
    asm volatile("cp.async.cg.shared.global [%0], [%1], 16, %2;" :: "r"(dst), "l"(src), "r"(sz))
#define CP_COMMIT() asm volatile("cp.async.commit_group;")
#define CP_WAIT(n)  asm volatile("cp.async.wait_group %0;" :: "n"(n))

// ---------------- prep: weights + x tf32 rounding ---------------------------
__global__ void wprep_kernel(const float* __restrict__ wfx,
                             const float* __restrict__ wx)
{
    int idx = blockIdx.x * 256 + threadIdx.x;
    if (idx >= 1179648) return;
    int co = idx / 1152;
    int k  = idx - co * 1152;
    const float* w = (co < 512) ? wfx : wx;
    int c = (co < 512) ? co : co - 512;
    g_wt[idx] = __uint_as_float(cvt_tf32(w[(size_t)k * 512 + c]));
}
__global__ void wprep_x_kernel(const float* __restrict__ x)
{
    int idx = (blockIdx.x * 256 + threadIdx.x) * 4;
    float4 v = *(const float4*)(x + idx);
    uint4 u;
    u.x = cvt_tf32(v.x); u.y = cvt_tf32(v.y);
    u.z = cvt_tf32(v.z); u.w = cvt_tf32(v.w);
    *(uint4*)(g_xr + idx) = u;
}

// ---------------- conv: implicit GEMM, A-row-window reuse, 2 CTAs/SM ---------
// grid (1024 rows, 8 ctiles of 128co), 256 threads, warp tile 64x32.
// k-loop order (dy, ci, dx): A row-window (130px x 32ci) loaded once per
// (dy,ci), served to 3 dx shifts. A 2x19KB, B 3x18KB = 93KB -> 2 CTAs/SM.
#define A_STRIDE 36
#define A_BUF    4752          // 132 * 36 floats
#define B_BASE   9504
#define B_STAGE  4608          // 128 * 36 floats
__global__ void __launch_bounds__(256, 2)
conv_mma_kernel(const float* __restrict__ bfx, const float* __restrict__ bx)
{
    extern __shared__ float sm[];
    const int tid  = threadIdx.x;
    const int wid  = tid >> 5;
    const int lane = tid & 31;
    const int g    = lane >> 2;
    const int t4   = lane & 3;
    const int warpM = wid & 1;     // 2 M-groups of 64
    const int warpN = wid >> 1;    // 4 N-groups of 32

    const int row = blockIdx.x;
    const int b   = row >> 7;
    const int y   = row & 127;
    const int ct  = blockIdx.y;          // 0..7 (0-3 fx, 4-7 xm)
    const int co0 = ct * 128;

    float acc[4][4][4] = {};

    // A window for oi = dy*4+ci: rows 0..129 <-> px -1..128, 32 ci columns
    auto load_A = [&](int oi, int buf) {
        float* base = sm + buf * A_BUF;
        const int dy = oi >> 2;
        const int ci0 = (oi & 3) * 32;
        const int yy = y + dy - 1;
        const bool yok = (unsigned)yy < 128u;
        const float* xb = g_xr + ((size_t)(b * 128 + (yok ? yy : 0)) * 128) * 128 + ci0;
        #pragma unroll
        for (int i = 0; i < 5; ++i) {
            int f = tid + 256 * i;
            if (f < 1040) {                     // 130 rows x 8 float4
                int r = f >> 3, q = f & 7;
                int xp = r - 1;
                bool ok = yok && (unsigned)xp < 128u;
                const float* src = xb + (size_t)(ok ? xp : 0) * 128 + q * 4;
                CP16Z(smem_u32(base + r * A_STRIDE + q * 4), src, ok ? 16 : 0);
            }
        }
    };
    auto load_B = [&](int cc) {
        float* base = sm + B_BASE + (cc % 3) * B_STAGE;
        const int oi2 = cc / 3;
        const int tap = (oi2 >> 2) * 3 + cc % 3;
        const int k0w = tap * 128 + (oi2 & 3) * 32;
        #pragma unroll
        for (int i = 0; i < 4; ++i) {
            int f = tid + 256 * i;
            int r = f >> 3, q = f & 7;
            const float* src = g_wt + (size_t)(co0 + r) * 1152 + k0w + q * 4;
            CP16(smem_u32(base + r * A_STRIDE + q * 4), src);
        }
    };
    auto compute = [&](int c) {
        const int oi = c / 3;
        const int shift = c % 3;                // dx + 1
        const float* As_ = sm + (oi & 1) * A_BUF + shift * A_STRIDE;
        const float* Bs_ = sm + B_BASE + (c % 3) * B_STAGE;
        const int m0 = warpM * 64;
        const int n0 = warpN * 32;
        #pragma unroll
        for (int ks = 0; ks < 4; ++ks) {
            const int kk = ks * 8;
            unsigned af[4][4];
            #pragma unroll
            for (int mt = 0; mt < 4; ++mt) {
                const float* p0 = As_ + (m0 + mt * 16 + g) * A_STRIDE + kk + t4;
                const float* p1 = p0 + 8 * A_STRIDE;
                af[mt][0] = __float_as_uint(p0[0]);
                af[mt][1] = __float_as_uint(p1[0]);
                af[mt][2] = __float_as_uint(p0[4]);
                af[mt][3] = __float_as_uint(p1[4]);
            }
            unsigned bf[4][2];
            #pragma unroll
            for (int nt = 0; nt < 4; ++nt) {
                const float* p = Bs_ + (n0 + nt * 8 + g) * A_STRIDE + kk + t4;
                bf[nt][0] = __float_as_uint(p[0]);
                bf[nt][1] = __float_as_uint(p[4]);
            }
            #pragma unroll
            for (int mt = 0; mt < 4; ++mt)
                #pragma unroll
                for (int nt = 0; nt < 4; ++nt)
                    mma_tf32(acc[mt][nt], af[mt], bf[nt]);
        }
    };

    // prologue: group0 = {A(0), B(0)}, group1 = {B(1)}
    load_A(0, 0); load_B(0); CP_COMMIT();
    load_B(1); CP_COMMIT();

    for (int c = 0; c < 36; ++c) {
        if (c < 35) { CP_WAIT(1); } else { CP_WAIT(0); }
        __syncthreads();
        const int cc = c + 2;
        if (cc < 36) {
            if (cc % 3 == 0) load_A(cc / 3, (cc / 3) & 1);
            load_B(cc);
            CP_COMMIT();
        }
        compute(c);
    }

    if (ct < 4) {
        // fx: transpose in smem, write (B,512co,16384n) coalesced
        __syncthreads();
        float* T = sm;                  // [128 co][132]
        #pragma unroll
        for (int mt = 0; mt < 4; ++mt) {
            const int m = warpM * 64 + mt * 16 + g;
            #pragma unroll
            for (int nt = 0; nt < 4; ++nt) {
                const int nl = warpN * 32 + nt * 8 + t4 * 2;
                T[(size_t)nl * 132 + m]           = acc[mt][nt][0];
                T[(size_t)(nl + 1) * 132 + m]     = acc[mt][nt][1];
                T[(size_t)nl * 132 + m + 8]       = acc[mt][nt][2];
                T[(size_t)(nl + 1) * 132 + m + 8] = acc[mt][nt][3];
            }
        }
        __syncthreads();
        const float* biasp = bfx + ct * 128;
        float* dst = g_fxt + ((size_t)b * 512 + ct * 128) * 16384 + y * 128;
        #pragma unroll 4
        for (int r = 0; r < 16; ++r) {
            int co = wid * 16 + r;
            float bb = __ldg(biasp + co);
            float4 v = *(const float4*)&T[(size_t)co * 132 + lane * 4];
            v.x += bb; v.y += bb; v.z += bb; v.w += bb;
            *(float4*)(dst + (size_t)co * 16384 + lane * 4) = v;
        }
    } else {
        const int cin = (ct - 4) * 128;
        const float* biasp = bx + cin;
        float* outb = g_xm + ((size_t)(b * N_ + y * 128)) * 512 + cin;
        #pragma unroll
        for (int mt = 0; mt < 4; ++mt) {
            const int m = warpM * 64 + mt * 16 + g;
            #pragma unroll
            for (int nt = 0; nt < 4; ++nt) {
                const int nl = warpN * 32 + nt * 8 + t4 * 2;
                float b0 = __ldg(biasp + nl), b1 = __ldg(biasp + nl + 1);
                *(float2*)(outb + (size_t)m * 512 + nl) =
                    make_float2(acc[mt][nt][0] + b0, acc[mt][nt][1] + b1);
                *(float2*)(outb + (size_t)(m + 8) * 512 + nl) =
                    make_float2(acc[mt][nt][2] + b0, acc[mt][nt][3] + b1);
            }
        }
    }
}

// ---------------- slice weights: GEMM + softmax, 256-token tiles -------------
__global__ void __launch_bounds__(256)
sliceweights_kernel(const float* __restrict__ slice_w,
                    const float* __restrict__ slice_b,
                    const float* __restrict__ temperature)
{
    extern __shared__ float dsm[];
    float* Xst = dsm;            // [c][t], stride 260
    float* Wt  = dsm + 16640;    // [c][g], stride 68
    float* NP  = dsm + 20992;    // [warp][g]

    const int tid  = threadIdx.x;
    const int h    = blockIdx.y;
    const int b    = blockIdx.x >> 6;
    const int tile = blockIdx.x & 63;
    const int bn0  = b * N_ + tile * 256;
    const int nin  = tile * 256;

    for (int i = tid; i < 4096; i += 256) {
        int gg = i >> 6, c = i & 63;
        Wt[c * 68 + gg] = slice_w[i];
    }
    #pragma unroll
    for (int i = 0; i < 16; ++i) {
        int f = tid + 256 * i;
        int t = f >> 4, c4 = f & 15;
        float4 v = *(const float4*)(g_xm + (size_t)(bn0 + t) * 512 + h * 64 + c4 * 4);
        Xst[(c4 * 4 + 0) * 260 + t] = v.x;
        Xst[(c4 * 4 + 1) * 260 + t] = v.y;
        Xst[(c4 * 4 + 2) * 260 + t] = v.z;
        Xst[(c4 * 4 + 3) * 260 + t] = v.w;
    }
    __syncthreads();

    const int tx = tid & 7;
    const int ty = tid >> 3;
    const int t0 = ty * 8;
    const int g0 = tx * 8;
    const int lane = tid & 31;
    const int warp = tid >> 5;

    float acc[8][8] = {};
    #pragma unroll 2
    for (int c = 0; c < 64; ++c) {
        float4 a0 = *(const float4*)&Xst[c * 260 + t0];
        float4 a1 = *(const float4*)&Xst[c * 260 + t0 + 4];
        float4 b0 = *(const float4*)&Wt[c * 68 + g0];
        float4 b1 = *(const float4*)&Wt[c * 68 + g0 + 4];
        float av[8] = {a0.x, a0.y, a0.z, a0.w, a1.x, a1.y, a1.z, a1.w};
        #pragma unroll
        for (int i = 0; i < 8; ++i) {
            acc[i][0] += av[i] * b0.x; acc[i][1] += av[i] * b0.y;
            acc[i][2] += av[i] * b0.z; acc[i][3] += av[i] * b0.w;
            acc[i][4] += av[i] * b1.x; acc[i][5] += av[i] * b1.y;
            acc[i][6] += av[i] * b1.z; acc[i][7] += av[i] * b1.w;
        }
    }

    float tv = temperature[h];
    tv = fminf(fmaxf(tv, 0.1f), 5.0f);
    float invt = 1.f / tv;
    float bias[8];
    #pragma unroll
    for (int j = 0; j < 8; ++j) bias[j] = __ldg(slice_b + g0 + j);

    #pragma unroll
    for (int i = 0; i < 8; ++i) {
        float l[8];
        #pragma unroll
        for (int j = 0; j < 8; ++j) l[j] = (acc[i][j] + bias[j]) * invt;
        float mx = l[0];
        #pragma unroll
        for (int j = 1; j < 8; ++j) mx = fmaxf(mx, l[j]);
        #pragma unroll
        for (int o = 1; o < 8; o <<= 1)
            mx = fmaxf(mx, __shfl_xor_sync(0xffffffffu, mx, o));
        float s = 0.f;
        #pragma unroll
        for (int j = 0; j < 8; ++j) { l[j] = __expf(l[j] - mx); s += l[j]; }
        #pragma unroll
        for (int o = 1; o < 8; o <<= 1)
            s += __shfl_xor_sync(0xffffffffu, s, o);
        float inv = 1.f / s;
        #pragma unroll
        for (int j = 0; j < 8; ++j) acc[i][j] = l[j] * inv;
    }

    const int bh = b * 8 + h;
    float* gb = g_swt + (((size_t)bh * 64 + g0) * 16384) + nin + t0;
    #pragma unroll
    for (int j = 0; j < 8; ++j) {
        *(float4*)(gb + (size_t)j * 16384) =
            make_float4(acc[0][j], acc[1][j], acc[2][j], acc[3][j]);
        *(float4*)(gb + (size_t)j * 16384 + 4) =
            make_float4(acc[4][j], acc[5][j], acc[6][j], acc[7][j]);
    }

    float pn[8];
    #pragma unroll
    for (int j = 0; j < 8; ++j) {
        float p = acc[0][j] + acc[1][j] + acc[2][j] + acc[3][j]
                + acc[4][j] + acc[5][j] + acc[6][j] + acc[7][j];
        p += __shfl_xor_sync(0xffffffffu, p, 8);
        p += __shfl_xor_sync(0xffffffffu, p, 16);
        pn[j] = p;
    }
    if (lane < 8) {
        #pragma unroll
        for (int j = 0; j < 8; ++j) NP[warp * 64 + lane * 8 + j] = pn[j];
    }
    __syncthreads();
    if (tid < 64) {
        float s = 0.f;
        #pragma unroll
        for (int wv = 0; wv < 8; ++wv) s += NP[wv * 64 + tid];
        g_npart[((size_t)bh * 64 + tile) * 64 + tid] = s;
    }
}

// ---------------- slice_token: tf32 hi/lo mma GEMM over K=n ------------------
__global__ void __launch_bounds__(256)
slicetoken_kernel()
{
    extern __shared__ float sm2[];
    const int tid  = threadIdx.x;
    const int wid  = tid >> 5;
    const int lane = tid & 31;
    const int g    = lane >> 2;
    const int t4   = lane & 3;
    const int bh   = blockIdx.x;
    const int b    = bh >> 3, h = bh & 7;
    const int n0   = blockIdx.y * 1024;

    const float* arow = g_swt + (size_t)bh * 64 * 16384;
    const float* brow = g_fxt + ((size_t)b * 512 + h * 64) * 16384;

    auto load = [&](int kt, int s) {
        float* base = sm2 + s * 8704;
        const int nn = n0 + kt * 64;
        #pragma unroll
        for (int i = 0; i < 4; ++i) {
            int f = tid + 256 * i;
            int r = f >> 4, q = f & 15;
            CP16(smem_u32(base + r * 68 + q * 4),
                 arow + (size_t)r * 16384 + nn + q * 4);
            CP16(smem_u32(base + 4352 + r * 68 + q * 4),
                 brow + (size_t)r * 16384 + nn + q * 4);
        }
    };

    float acc[4][4] = {};
    const int m0  = (wid & 3) * 16;
    const int nc0 = (wid >> 2) * 32;

    load(0, 0); CP_COMMIT();
    for (int kt = 0; kt < 16; ++kt) {
        CP_WAIT(0);
        __syncthreads();
        if (kt + 1 < 16) { load(kt + 1, (kt + 1) & 1); CP_COMMIT(); }
        const float* As_ = sm2 + (kt & 1) * 8704;
        const float* Bs_ = As_ + 4352;
        #pragma unroll
        for (int ks = 0; ks < 8; ++ks) {
            const int kk = ks * 8;
            unsigned afh[4], afl[4];
            const float* p0 = As_ + (m0 + g) * 68 + kk + t4;
            const float* p1 = p0 + 544;
            split_tf32(p0[0], afh[0], afl[0]);
            split_tf32(p1[0], afh[1], afl[1]);
            split_tf32(p0[4], afh[2], afl[2]);
            split_tf32(p1[4], afh[3], afl[3]);
            #pragma unroll
            for (int nt = 0; nt < 4; ++nt) {
                unsigned bfh[2], bfl[2];
                const float* p = Bs_ + (nc0 + nt * 8 + g) * 68 + kk + t4;
                split_tf32(p[0], bfh[0], bfl[0]);
                split_tf32(p[4], bfh[1], bfl[1]);
                mma_tf32(acc[nt], afh, bfh);
                mma_tf32(acc[nt], afl, bfh);
                mma_tf32(acc[nt], afh, bfl);
            }
        }
    }

    float* p = g_part + ((size_t)blockIdx.y * 64 + bh) * 4096;
    #pragma unroll
    for (int nt = 0; nt < 4; ++nt) {
        const int col = nc0 + nt * 8 + t4 * 2;
        *(float2*)(p + (m0 + g) * 64 + col)     = make_float2(acc[nt][0], acc[nt][1]);
        *(float2*)(p + (m0 + 8 + g) * 64 + col) = make_float2(acc[nt][2], acc[nt][3]);
    }
}

// ---------------- reduce partials --------------------------------------------
__global__ void reduce_token_kernel()
{
    int idx = blockIdx.x * 512 + threadIdx.x;
    float s = 0.f;
    #pragma unroll
    for (int ch = 0; ch < 16; ++ch) s += g_part[(size_t)ch * 262144 + idx];
    g_st[idx] = s;
    if (idx < 4096) {
        int bh = idx >> 6, gg = idx & 63;
        float ns = 0.f;
        for (int t = 0; t < 64; ++t)
            ns += g_npart[((size_t)bh * 64 + t) * 64 + gg];
        g_norm[idx] = ns;
    }
}

// ---------------- normalize + QKV --------------------------------------------
__global__ void qkv_kernel(const float* __restrict__ wq,
                           const float* __restrict__ wk,
                           const float* __restrict__ wv)
{
    __shared__ float S[64][65];
    int bh = blockIdx.x;
    int tid = threadIdx.x;
    const float* st = g_st + (size_t)bh * 4096;
    const float* nm = g_norm + bh * 64;
    for (int i = tid; i < 4096; i += 256)
        S[i >> 6][i & 63] = st[i] / (nm[i >> 6] + 1e-5f);
    __syncthreads();

    int g = tid >> 2;
    int d0 = (tid & 3) * 16;
    for (int d = d0; d < d0 + 16; ++d) {
        float q = 0.f, k = 0.f, v = 0.f;
        #pragma unroll 8
        for (int c = 0; c < 64; ++c) {
            float s = S[g][c];
            q += s * wq[d * 64 + c];
            k += s * wk[d * 64 + c];
            v += s * wv[d * 64 + c];
        }
        int o = bh * 4096 + g * 64 + d;
        g_q[o] = q; g_k[o] = k; g_v[o] = v;
    }
}

// ---------------- 64x64 attention per (b,h) ----------------------------------
__global__ void attn_kernel()
{
    __shared__ float X[64][65];
    __shared__ float Y[64][65];
    int bh = blockIdx.x;
    int tid = threadIdx.x;
    for (int i = tid; i < 4096; i += 256) {
        X[i >> 6][i & 63] = g_q[bh * 4096 + i];
        Y[i >> 6][i & 63] = g_k[bh * 4096 + i];
    }
    __syncthreads();

    int g = tid >> 2;
    int k0 = (tid & 3) * 16;
    float a[16];
    #pragma unroll
    for (int i = 0; i < 16; ++i) {
        float s = 0.f;
        for (int c = 0; c < 64; ++c) s += X[g][c] * Y[k0 + i][c];
        a[i] = s * 0.125f;
    }
    __syncthreads();
    #pragma unroll
    for (int i = 0; i < 16; ++i) X[g][k0 + i] = a[i];
    for (int i = tid; i < 4096; i += 256)
        Y[i >> 6][i & 63] = g_v[bh * 4096 + i];
    __syncthreads();

    if (tid < 64) {
        float mx = -1e30f;
        for (int k = 0; k < 64; ++k) mx = fmaxf(mx, X[tid][k]);
        float s = 0.f;
        for (int k = 0; k < 64; ++k) { float e = __expf(X[tid][k] - mx); X[tid][k] = e; s += e; }
        float inv = 1.f / s;
        for (int k = 0; k < 64; ++k) X[tid][k] *= inv;
    }
    __syncthreads();

    for (int d = k0; d < k0 + 16; ++d) {
        float o = 0.f;
        for (int k = 0; k < 64; ++k) o += X[g][k] * Y[k][d];
        g_os[bh * 4096 + g * 64 + d] = o;
    }
}

// ---------------- OW: fold out_slice through out_w ---------------------------
__global__ void ow_kernel(const float* __restrict__ out_w)
{
    __shared__ float OS[64][65];
    __shared__ float W[64][65];
    const int bh = blockIdx.x;
    const int h  = bh & 7;
    const int tid = threadIdx.x;

    for (int i = tid; i < 4096; i += 256)
        OS[i >> 6][i & 63] = g_os[(size_t)bh * 4096 + i];

    const int ty = tid >> 5;
    const int tx = tid & 31;
    const int dd0 = ty * 8;
    const int gg0 = tx * 2;

    #pragma unroll
    for (int half = 0; half < 2; ++half) {
        const int d0 = half * 64;
        __syncthreads();
        for (int i = tid; i < 4096; i += 256) {
            int dd = i >> 6, c = i & 63;
            W[dd][c] = out_w[(size_t)(d0 + dd) * 512 + h * 64 + c];
        }
        __syncthreads();

        float acc[2][8] = {};
        #pragma unroll 4
        for (int c = 0; c < 64; ++c) {
            float o0 = OS[gg0][c], o1 = OS[gg0 + 1][c];
            #pragma unroll
            for (int dd = 0; dd < 8; ++dd) {
                float wv = W[dd0 + dd][c];
                acc[0][dd] += o0 * wv;
                acc[1][dd] += o1 * wv;
            }
        }
        #pragma unroll
        for (int i = 0; i < 2; ++i) {
            float* dst = g_ow + ((size_t)bh * 64 + gg0 + i) * 128 + d0 + dd0;
            *(float4*)dst = make_float4(acc[i][0], acc[i][1], acc[i][2], acc[i][3]);
            *(float4*)(dst + 4) = make_float4(acc[i][4], acc[i][5], acc[i][6], acc[i][7]);
        }
    }
}

// ---------------- fused final: out = swt^T @ OW + out_b (full 128-d tile) ----
__global__ void final_kernel(const float* __restrict__ out_b,
                             float* __restrict__ out)
{
    __shared__ float As[32][68];
    __shared__ float Bs[32][132];
    const int b     = blockIdx.x >> 8;
    const int m0    = (blockIdx.x & 255) * 64;
    const int tid   = threadIdx.x;
    const int ty = tid >> 4, tx = tid & 15;
    float acc[4][8] = {};

    const float* abase = g_swt + (size_t)b * 512 * 16384;
    const float* bbase = g_ow + (size_t)b * 512 * 128;

    for (int k0 = 0; k0 < 512; k0 += 32) {
        #pragma unroll
        for (int i = 0; i < 2; ++i) {
            int f = tid + 256 * i;
            int r = f >> 4, q = f & 15;
            float4 v = *(const float4*)(abase + (size_t)(k0 + r) * 16384 + m0 + q * 4);
            *(float4*)&As[r][q * 4] = v;
        }
        #pragma unroll
        for (int i = 0; i < 4; ++i) {
            int f = tid + 256 * i;
            int r = f >> 5, q = f & 31;
            float4 v = *(const float4*)(bbase + (size_t)(k0 + r) * 128 + q * 4);
            *(float4*)&Bs[r][q * 4] = v;
        }
        __syncthreads();
        #pragma unroll
        for (int kk = 0; kk < 32; ++kk) {
            float4 a   = *(const float4*)&As[kk][ty * 4];
            float4 bv0 = *(const float4*)&Bs[kk][tx * 4];
            float4 bv1 = *(const float4*)&Bs[kk][64 + tx * 4];
            acc[0][0] += a.x * bv0.x; acc[0][1] += a.x * bv0.y; acc[0][2] += a.x * bv0.z; acc[0][3] += a.x * bv0.w;
            acc[1][0] += a.y * bv0.x; acc[1][1] += a.y * bv0.y; acc[1][2] += a.y * bv0.z; acc[1][3] += a.y * bv0.w;
            acc[2][0] += a.z * bv0.x; acc[2][1] += a.z * bv0.y; acc[2][2] += a.z * bv0.z; acc[2][3] += a.z * bv0.w;
            acc[3][0] += a.w * bv0.x; acc[3][1] += a.w * bv0.y; acc[3][2] += a.w * bv0.z; acc[3][3] += a.w * bv0.w;
            acc[0][4] += a.x * bv1.x; acc[0][5] += a.x * bv1.y; acc[0][6] += a.x * bv1.z; acc[0][7] += a.x * bv1.w;
            acc[1][4] += a.y * bv1.x; acc[1][5] += a.y * bv1.y; acc[1][6] += a.y * bv1.z; acc[1][7] += a.y * bv1.w;
            acc[2][4] += a.z * bv1.x; acc[2][5] += a.z * bv1.y; acc[2][6] += a.z * bv1.z; acc[2][7] += a.z * bv1.w;
            acc[3][4] += a.w * bv1.x; acc[3][5] += a.w * bv1.y; acc[3][6] += a.w * bv1.z; acc[3][7] += a.w * bv1.w;
        }
        __syncthreads();
    }
    #pragma unroll
    for (int i = 0; i < 4; ++i) {
        int n = m0 + ty * 4 + i;
        float* o = out + ((size_t)(b * N_ + n)) * 128;
        #pragma unroll
        for (int j = 0; j < 4; ++j) {
            o[tx * 4 + j]      = acc[i][j]     + __ldg(out_b + tx * 4 + j);
            o[64 + tx * 4 + j] = acc[i][4 + j] + __ldg(out_b + 64 + tx * 4 + j);
        }
    }
}

// ---------------- launch ------------------------------------------------------
extern "C" void kernel_launch(void* const* d_in, const int* in_sizes, int n_in,
                              void* d_out, int out_size)
{
    const float* x          = (const float*)d_in[0];
    const float* conv_fx_w  = (const float*)d_in[1];
    const float* conv_fx_b  = (const float*)d_in[2];
    const float* conv_x_w   = (const float*)d_in[3];
    const float* conv_x_b   = (const float*)d_in[4];
    const float* slice_w    = (const float*)d_in[5];
    const float* slice_b    = (const float*)d_in[6];
    const float* temperature= (const float*)d_in[7];
    const float* wq         = (const float*)d_in[8];
    const float* wk         = (const float*)d_in[9];
    const float* wv         = (const float*)d_in[10];
    const float* out_w      = (const float*)d_in[11];
    const float* out_b      = (const float*)d_in[12];
    float* out = (float*)d_out;

    // conv smem: 9504 + 3*4608 = 23328 floats = 93312 B
    cudaFuncSetAttribute(conv_mma_kernel,
                         cudaFuncAttributeMaxDynamicSharedMemorySize, 93312);
    cudaFuncSetAttribute(sliceweights_kernel,
                         cudaFuncAttributeMaxDynamicSharedMemorySize, 86016);
    cudaFuncSetAttribute(slicetoken_kernel,
                         cudaFuncAttributeMaxDynamicSharedMemorySize, 69632);

    wprep_kernel<<<4608, 256>>>(conv_fx_w, conv_x_w);
    wprep_x_kernel<<<16384, 256>>>(x);
    conv_mma_kernel<<<dim3(1024, 8), 256, 93312>>>(conv_fx_b, conv_x_b);
    sliceweights_kernel<<<dim3(512, 8), 256, 86016>>>(slice_w, slice_b, temperature);
    slicetoken_kernel<<<dim3(64, 16), 256, 69632>>>();
    reduce_token_kernel<<<512, 512>>>();
    qkv_kernel<<<64, 256>>>(wq, wk, wv);
    attn_kernel<<<64, 256>>>();
    ow_kernel<<<64, 256>>>(out_w);
    final_kernel<<<2048, 256>>>(out_b, out);
}